// round 7
// baseline (speedup 1.0000x reference)
#include <cuda_runtime.h>
#include <cuda_bf16.h>

#define N_NODES 100000
#define N_EDGES 1600000
#define IN_DIM  128
#define HID_DIM 64
#define OUT_DIM 40
#define SCAN_T  1024

// ---------------- scratch (static device globals; no runtime alloc) --------
__device__              int    g_is64;
__device__              int    g_cnt [N_NODES];      // in-degree (edges only)
__device__              int    g_rs  [N_NODES + 1];  // CSR row start
__device__              int    g_cur [N_NODES];      // fill cursor
__device__ __align__(16) float g_dinv[N_NODES];
__device__              int    g_src [N_EDGES];
__device__              int    g_dst [N_EDGES];
__device__ __align__(8)  int2  g_csr [N_EDGES];      // {src, bits(dinv[src])}
__device__ __align__(16) float g_h1  [(size_t)N_NODES * HID_DIM];   // x@W1
__device__ __align__(16) float g_agg1[(size_t)N_NODES * HID_DIM];   // layer1 agg
__device__ __align__(16) float g_h2  [(size_t)N_NODES * OUT_DIM];   // relu(agg1+b1)@W2

// ---------------- dtype detection: int32 vs int64 edge_index ---------------
__global__ void k_detect(const unsigned* __restrict__ w) {
    if (threadIdx.x == 0 && blockIdx.x == 0) {
        int all0 = 1;
        for (int i = 0; i < 64; i++)
            if (w[2 * i + 1] != 0u) { all0 = 0; break; }
        g_is64 = all0;
    }
}

__global__ void k_zero_cnt() {
    int i = blockIdx.x * blockDim.x + threadIdx.x;
    if (i < N_NODES) g_cnt[i] = 0;
}

// extract src/dst as int32 (either stored width) + histogram by dst
__global__ void k_extract(const unsigned* __restrict__ w) {
    int e = blockIdx.x * blockDim.x + threadIdx.x;
    if (e >= N_EDGES) return;
    int s, d;
    if (g_is64) {
        s = (int)w[2 * e];                           // low word of int64
        d = (int)w[2 * (N_EDGES + e)];
    } else {
        s = (int)w[e];
        d = (int)w[N_EDGES + e];
    }
    g_src[e] = s;
    g_dst[e] = d;
    atomicAdd(&g_cnt[d], 1);                         // REDG int
}

__global__ void k_rsqrt() {
    int i = blockIdx.x * blockDim.x + threadIdx.x;
    if (i < N_NODES) g_dinv[i] = rsqrtf((float)g_cnt[i] + 1.0f);  // + self loop
}

// single-block exclusive scan of g_cnt -> g_rs / g_cur
__global__ __launch_bounds__(SCAN_T) void k_scan() {
    __shared__ int part[SCAN_T];
    int t = threadIdx.x;
    const int chunk = (N_NODES + SCAN_T - 1) / SCAN_T;   // 98
    int lo = t * chunk;
    int hi = min(lo + chunk, N_NODES);
    int sum = 0;
    for (int i = lo; i < hi; i++) sum += g_cnt[i];
    part[t] = sum;
    __syncthreads();
    for (int off = 1; off < SCAN_T; off <<= 1) {
        int other = (t >= off) ? part[t - off] : 0;
        __syncthreads();
        part[t] += other;
        __syncthreads();
    }
    int run = part[t] - sum;                             // exclusive offset
    for (int i = lo; i < hi; i++) {
        g_rs[i]  = run;
        g_cur[i] = run;
        run += g_cnt[i];
    }
    if (t == SCAN_T - 1) g_rs[N_NODES] = run;
}

// scatter edges into CSR slots
__global__ void k_fill() {
    int e = blockIdx.x * blockDim.x + threadIdx.x;
    if (e >= N_EDGES) return;
    int s = g_src[e];
    int d = g_dst[e];
    int slot = atomicAdd(&g_cur[d], 1);
    g_csr[slot] = make_int2(s, __float_as_int(g_dinv[s]));
}

// ---------------- layer 1 GEMM: h1 = x @ W1 --------------------------------
__global__ __launch_bounds__(256) void k_gemm1(const float* __restrict__ x,
                                               const float* __restrict__ W1) {
    __shared__ float Ws[IN_DIM * HID_DIM];          // 32 KB
    {
        float4* dsh = (float4*)Ws;
        const float4* ssh = (const float4*)W1;
        for (int i = threadIdx.x; i < IN_DIM * HID_DIM / 4; i += blockDim.x)
            dsh[i] = ssh[i];
    }
    __syncthreads();

    int node = blockIdx.x * blockDim.x + threadIdx.x;
    if (node >= N_NODES) return;

    float acc[HID_DIM];
#pragma unroll
    for (int j = 0; j < HID_DIM; j++) acc[j] = 0.0f;

    const float4* xr = (const float4*)(x + (size_t)node * IN_DIM);
#pragma unroll 2
    for (int kk = 0; kk < IN_DIM / 4; ++kk) {
        float4 xv = xr[kk];
        float xs[4] = {xv.x, xv.y, xv.z, xv.w};
#pragma unroll
        for (int q = 0; q < 4; ++q) {
            const float4* wr = (const float4*)&Ws[(kk * 4 + q) * HID_DIM];
#pragma unroll
            for (int j4 = 0; j4 < HID_DIM / 4; ++j4) {
                float4 w = wr[j4];                  // warp-broadcast LDS
                acc[4 * j4 + 0] += xs[q] * w.x;
                acc[4 * j4 + 1] += xs[q] * w.y;
                acc[4 * j4 + 2] += xs[q] * w.z;
                acc[4 * j4 + 3] += xs[q] * w.w;
            }
        }
    }

    size_t base = (size_t)node * HID_DIM;
#pragma unroll
    for (int j4 = 0; j4 < HID_DIM / 4; ++j4) {
        float4 h;
        h.x = acc[4 * j4 + 0]; h.y = acc[4 * j4 + 1];
        h.z = acc[4 * j4 + 2]; h.w = acc[4 * j4 + 3];
        *(float4*)&g_h1[base + 4 * j4] = h;
    }
}

// -------- layer 1 aggregation: CSR gather, register accumulate -------------
// 16 threads per node, one float4 chunk each.
__global__ __launch_bounds__(256) void k_agg1csr() {
    int idx = blockIdx.x * blockDim.x + threadIdx.x;
    int node = idx >> 4;
    if (node >= N_NODES) return;
    int c = (idx & 15) << 2;

    float dd = g_dinv[node];
    float4 self = *(const float4*)&g_h1[(size_t)node * HID_DIM + c];
    float sl = dd * dd;
    float ax = self.x * sl, ay = self.y * sl, az = self.z * sl, aw = self.w * sl;

    int lo = g_rs[node];
    int hi = g_rs[node + 1];
    for (int j = lo; j < hi; j++) {
        int2 ent = g_csr[j];                        // broadcast across 16 lanes
        float w = __int_as_float(ent.y) * dd;       // dinv[s] * dinv[d]
        float4 v = *(const float4*)&g_h1[(size_t)ent.x * HID_DIM + c];
        ax += v.x * w; ay += v.y * w; az += v.z * w; aw += v.w * w;
    }
    float4 o; o.x = ax; o.y = ay; o.z = az; o.w = aw;
    *(float4*)&g_agg1[(size_t)node * HID_DIM + c] = o;
}

// ------------ layer 2 GEMM: h2 = relu(agg1 + b1) @ W2 ----------------------
__global__ __launch_bounds__(256) void k_gemm2(const float* __restrict__ W2,
                                               const float* __restrict__ b1) {
    __shared__ float Ws[HID_DIM * OUT_DIM];         // 10 KB
    __shared__ float b1s[HID_DIM];
    for (int i = threadIdx.x; i < HID_DIM * OUT_DIM; i += blockDim.x) Ws[i] = W2[i];
    for (int i = threadIdx.x; i < HID_DIM; i += blockDim.x) b1s[i] = b1[i];
    __syncthreads();

    int node = blockIdx.x * blockDim.x + threadIdx.x;
    if (node >= N_NODES) return;

    float acc[OUT_DIM];
#pragma unroll
    for (int j = 0; j < OUT_DIM; j++) acc[j] = 0.0f;

    size_t ibase = (size_t)node * HID_DIM;
#pragma unroll 2
    for (int k4 = 0; k4 < HID_DIM / 4; ++k4) {
        float4 a = *(const float4*)&g_agg1[ibase + 4 * k4];
        float vin[4];
        vin[0] = fmaxf(a.x + b1s[4 * k4 + 0], 0.0f);
        vin[1] = fmaxf(a.y + b1s[4 * k4 + 1], 0.0f);
        vin[2] = fmaxf(a.z + b1s[4 * k4 + 2], 0.0f);
        vin[3] = fmaxf(a.w + b1s[4 * k4 + 3], 0.0f);
#pragma unroll
        for (int q = 0; q < 4; ++q) {
            const float4* wr = (const float4*)&Ws[(4 * k4 + q) * OUT_DIM];
#pragma unroll
            for (int j4 = 0; j4 < OUT_DIM / 4; ++j4) {
                float4 w = wr[j4];
                acc[4 * j4 + 0] += vin[q] * w.x;
                acc[4 * j4 + 1] += vin[q] * w.y;
                acc[4 * j4 + 2] += vin[q] * w.z;
                acc[4 * j4 + 3] += vin[q] * w.w;
            }
        }
    }

    size_t ob = (size_t)node * OUT_DIM;
#pragma unroll
    for (int j4 = 0; j4 < OUT_DIM / 4; ++j4) {
        float4 h;
        h.x = acc[4 * j4 + 0]; h.y = acc[4 * j4 + 1];
        h.z = acc[4 * j4 + 2]; h.w = acc[4 * j4 + 3];
        *(float4*)&g_h2[ob + 4 * j4] = h;
    }
}

// -------- layer 2 aggregation: CSR gather, writes final out ----------------
// 10 threads per node, one float4 chunk each.
__global__ __launch_bounds__(250) void k_agg2csr(const float* __restrict__ b2,
                                                 float* __restrict__ out) {
    int idx = blockIdx.x * blockDim.x + threadIdx.x;
    int node = idx / 10;
    if (node >= N_NODES) return;
    int c = (idx - node * 10) * 4;

    float dd = g_dinv[node];
    float4 self = *(const float4*)&g_h2[(size_t)node * OUT_DIM + c];
    float sl = dd * dd;
    float ax = self.x * sl, ay = self.y * sl, az = self.z * sl, aw = self.w * sl;

    int lo = g_rs[node];
    int hi = g_rs[node + 1];
    for (int j = lo; j < hi; j++) {
        int2 ent = g_csr[j];
        float w = __int_as_float(ent.y) * dd;
        float4 v = *(const float4*)&g_h2[(size_t)ent.x * OUT_DIM + c];
        ax += v.x * w; ay += v.y * w; az += v.z * w; aw += v.w * w;
    }
    float4 o;
    o.x = ax + b2[c + 0];
    o.y = ay + b2[c + 1];
    o.z = az + b2[c + 2];
    o.w = aw + b2[c + 3];
    *(float4*)&out[(size_t)node * OUT_DIM + c] = o;
}

// ---------------- launcher -------------------------------------------------
extern "C" void kernel_launch(void* const* d_in, const int* in_sizes, int n_in,
                              void* d_out, int out_size) {
    const float*    x  = (const float*)d_in[0];
    const unsigned* ei = (const unsigned*)d_in[1];   // int32 OR int64 words
    const float*    W1 = (const float*)d_in[2];
    const float*    b1 = (const float*)d_in[3];
    const float*    W2 = (const float*)d_in[4];
    const float*    b2 = (const float*)d_in[5];
    float* out = (float*)d_out;

    const int T = 256;
    k_detect  <<<1, 32>>>(ei);
    k_zero_cnt<<<(N_NODES + T - 1) / T, T>>>();
    k_extract <<<(N_EDGES + T - 1) / T, T>>>(ei);
    k_rsqrt   <<<(N_NODES + T - 1) / T, T>>>();
    k_scan    <<<1, SCAN_T>>>();
    k_fill    <<<(N_EDGES + T - 1) / T, T>>>();
    k_gemm1   <<<(N_NODES + T - 1) / T, T>>>(x, W1);
    k_agg1csr <<<(N_NODES * 16 + T - 1) / T, T>>>();
    k_gemm2   <<<(N_NODES + T - 1) / T, T>>>(W2, b1);
    k_agg2csr <<<(N_NODES * 10 + 249) / 250, 250>>>(b2, out);
}

// round 8
// speedup vs baseline: 1.0670x; 1.0670x over previous
#include <cuda_runtime.h>
#include <cuda_bf16.h>

#define N_NODES 100000
#define N_EDGES 1600000
#define IN_DIM  128
#define HID_DIM 64
#define OUT_DIM 40

// ---------------- scratch (static device globals; no runtime alloc) --------
__device__              int    g_is64;
__device__ __align__(16) float g_deg [N_NODES];
__device__ __align__(16) float g_dinv[N_NODES];
__device__              int    g_src [N_EDGES];
__device__              int    g_dst [N_EDGES];
__device__ __align__(16) int4  g_em  [N_EDGES];      // {src, dst, bits(norm), 0}
__device__ __align__(16) float g_h1  [(size_t)N_NODES * HID_DIM];   // x@W1
__device__ __align__(16) float g_agg1[(size_t)N_NODES * HID_DIM];   // layer1 agg
__device__ __align__(16) float g_h2  [(size_t)N_NODES * OUT_DIM];   // relu(agg1+b1)@W2

__device__ __forceinline__ void redg_f32(float* p, float v) {
    asm volatile("red.global.add.f32 [%0], %1;" :: "l"(p), "f"(v) : "memory");
}
__device__ __forceinline__ void redg_v4(float* p, float a, float b, float c, float d) {
    asm volatile("red.global.add.v4.f32 [%0], {%1, %2, %3, %4};"
                 :: "l"(p), "f"(a), "f"(b), "f"(c), "f"(d) : "memory");
}

// ---------------- dtype detection: int32 vs int64 edge_index ---------------
__global__ void k_detect(const unsigned* __restrict__ w) {
    if (threadIdx.x == 0 && blockIdx.x == 0) {
        int all0 = 1;
        for (int i = 0; i < 64; i++)
            if (w[2 * i + 1] != 0u) { all0 = 0; break; }
        g_is64 = all0;
    }
}

__global__ void k_init_deg() {
    int i = blockIdx.x * blockDim.x + threadIdx.x;
    if (i < N_NODES) g_deg[i] = 1.0f;               // implicit self loop
}

// extract src/dst as int32 (either stored width) + accumulate degree
__global__ void k_extract(const unsigned* __restrict__ w) {
    int e = blockIdx.x * blockDim.x + threadIdx.x;
    if (e >= N_EDGES) return;
    int s, d;
    if (g_is64) {
        s = (int)w[2 * e];                           // low word of int64
        d = (int)w[2 * (N_EDGES + e)];
    } else {
        s = (int)w[e];
        d = (int)w[N_EDGES + e];
    }
    g_src[e] = s;
    g_dst[e] = d;
    redg_f32(&g_deg[d], 1.0f);
}

__global__ void k_rsqrt() {
    int i = blockIdx.x * blockDim.x + threadIdx.x;
    if (i < N_NODES) g_dinv[i] = rsqrtf(g_deg[i]);
}

// pack {src, dst, norm} into one int4 per edge
__global__ void k_em() {
    int e = blockIdx.x * blockDim.x + threadIdx.x;
    if (e >= N_EDGES) return;
    int s = g_src[e];
    int d = g_dst[e];
    float nrm = g_dinv[s] * g_dinv[d];
    g_em[e] = make_int4(s, d, __float_as_int(nrm), 0);
}

// ---------------- layer 1 GEMM: h1 = x @ W1; agg1 init with self loop ------
__global__ __launch_bounds__(256) void k_gemm1(const float* __restrict__ x,
                                               const float* __restrict__ W1) {
    __shared__ float Ws[IN_DIM * HID_DIM];          // 32 KB
    {
        float4* dsh = (float4*)Ws;
        const float4* ssh = (const float4*)W1;
        for (int i = threadIdx.x; i < IN_DIM * HID_DIM / 4; i += blockDim.x)
            dsh[i] = ssh[i];
    }
    __syncthreads();

    int node = blockIdx.x * blockDim.x + threadIdx.x;
    if (node >= N_NODES) return;

    float acc[HID_DIM];
#pragma unroll
    for (int j = 0; j < HID_DIM; j++) acc[j] = 0.0f;

    const float4* xr = (const float4*)(x + (size_t)node * IN_DIM);
#pragma unroll 2
    for (int kk = 0; kk < IN_DIM / 4; ++kk) {
        float4 xv = xr[kk];
        float xs[4] = {xv.x, xv.y, xv.z, xv.w};
#pragma unroll
        for (int q = 0; q < 4; ++q) {
            const float4* wr = (const float4*)&Ws[(kk * 4 + q) * HID_DIM];
#pragma unroll
            for (int j4 = 0; j4 < HID_DIM / 4; ++j4) {
                float4 w = wr[j4];                  // warp-broadcast LDS
                acc[4 * j4 + 0] += xs[q] * w.x;
                acc[4 * j4 + 1] += xs[q] * w.y;
                acc[4 * j4 + 2] += xs[q] * w.z;
                acc[4 * j4 + 3] += xs[q] * w.w;
            }
        }
    }

    float di = g_dinv[node];
    float sl = di * di;                             // self-loop coefficient
    size_t base = (size_t)node * HID_DIM;
#pragma unroll
    for (int j4 = 0; j4 < HID_DIM / 4; ++j4) {
        float4 h;
        h.x = acc[4 * j4 + 0]; h.y = acc[4 * j4 + 1];
        h.z = acc[4 * j4 + 2]; h.w = acc[4 * j4 + 3];
        *(float4*)&g_h1[base + 4 * j4] = h;
        float4 a;
        a.x = h.x * sl; a.y = h.y * sl; a.z = h.z * sl; a.w = h.w * sl;
        *(float4*)&g_agg1[base + 4 * j4] = a;
    }
}

// ------- layer 1 edge aggregation: 4 threads/edge, 4 float4 chunks each ----
__global__ __launch_bounds__(256) void k_agg1() {
    int idx = blockIdx.x * blockDim.x + threadIdx.x;    // E * 4 threads
    int e = idx >> 2;
    if (e >= N_EDGES) return;
    int q = idx & 3;                                    // quarter of the row

    int4 em = g_em[e];                                  // broadcast across 4 lanes
    float nrm = __int_as_float(em.z);
    const float4* vp = (const float4*)&g_h1[(size_t)em.x * HID_DIM + q * 16];
    float4 v0 = vp[0];                                  // 4 independent gathers
    float4 v1 = vp[1];
    float4 v2 = vp[2];
    float4 v3 = vp[3];
    float* p = &g_agg1[(size_t)em.y * HID_DIM + q * 16];
    redg_v4(p +  0, v0.x * nrm, v0.y * nrm, v0.z * nrm, v0.w * nrm);
    redg_v4(p +  4, v1.x * nrm, v1.y * nrm, v1.z * nrm, v1.w * nrm);
    redg_v4(p +  8, v2.x * nrm, v2.y * nrm, v2.z * nrm, v2.w * nrm);
    redg_v4(p + 12, v3.x * nrm, v3.y * nrm, v3.z * nrm, v3.w * nrm);
}

// ------- layer 2 GEMM: h2 = relu(agg1 + b1) @ W2; out init = h2*d^2 + b2 ---
__global__ __launch_bounds__(256) void k_gemm2(const float* __restrict__ W2,
                                               const float* __restrict__ b1,
                                               const float* __restrict__ b2,
                                               float* __restrict__ out) {
    __shared__ float Ws[HID_DIM * OUT_DIM];         // 10 KB
    __shared__ float b1s[HID_DIM];
    __shared__ float b2s[OUT_DIM];
    for (int i = threadIdx.x; i < HID_DIM * OUT_DIM; i += blockDim.x) Ws[i] = W2[i];
    for (int i = threadIdx.x; i < HID_DIM; i += blockDim.x) b1s[i] = b1[i];
    for (int i = threadIdx.x; i < OUT_DIM; i += blockDim.x) b2s[i] = b2[i];
    __syncthreads();

    int node = blockIdx.x * blockDim.x + threadIdx.x;
    if (node >= N_NODES) return;

    float acc[OUT_DIM];
#pragma unroll
    for (int j = 0; j < OUT_DIM; j++) acc[j] = 0.0f;

    size_t ibase = (size_t)node * HID_DIM;
#pragma unroll 2
    for (int k4 = 0; k4 < HID_DIM / 4; ++k4) {
        float4 a = *(const float4*)&g_agg1[ibase + 4 * k4];
        float vin[4];
        vin[0] = fmaxf(a.x + b1s[4 * k4 + 0], 0.0f);
        vin[1] = fmaxf(a.y + b1s[4 * k4 + 1], 0.0f);
        vin[2] = fmaxf(a.z + b1s[4 * k4 + 2], 0.0f);
        vin[3] = fmaxf(a.w + b1s[4 * k4 + 3], 0.0f);
#pragma unroll
        for (int q = 0; q < 4; ++q) {
            const float4* wr = (const float4*)&Ws[(4 * k4 + q) * OUT_DIM];
#pragma unroll
            for (int j4 = 0; j4 < OUT_DIM / 4; ++j4) {
                float4 w = wr[j4];
                acc[4 * j4 + 0] += vin[q] * w.x;
                acc[4 * j4 + 1] += vin[q] * w.y;
                acc[4 * j4 + 2] += vin[q] * w.z;
                acc[4 * j4 + 3] += vin[q] * w.w;
            }
        }
    }

    float di = g_dinv[node];
    float sl = di * di;
    size_t ob = (size_t)node * OUT_DIM;
#pragma unroll
    for (int j4 = 0; j4 < OUT_DIM / 4; ++j4) {
        float4 h;
        h.x = acc[4 * j4 + 0]; h.y = acc[4 * j4 + 1];
        h.z = acc[4 * j4 + 2]; h.w = acc[4 * j4 + 3];
        *(float4*)&g_h2[ob + 4 * j4] = h;
        float4 o;
        o.x = h.x * sl + b2s[4 * j4 + 0];
        o.y = h.y * sl + b2s[4 * j4 + 1];
        o.z = h.z * sl + b2s[4 * j4 + 2];
        o.w = h.w * sl + b2s[4 * j4 + 3];
        *(float4*)&out[ob + 4 * j4] = o;
    }
}

// ------- layer 2 edge aggregation: 2 threads/edge, 5 float4 chunks each ----
__global__ __launch_bounds__(256) void k_agg2(float* __restrict__ out) {
    int idx = blockIdx.x * blockDim.x + threadIdx.x;    // E * 2 threads
    int e = idx >> 1;
    if (e >= N_EDGES) return;
    int q = idx & 1;                                    // half of the row

    int4 em = g_em[e];                                  // broadcast across 2 lanes
    float nrm = __int_as_float(em.z);
    const float4* vp = (const float4*)&g_h2[(size_t)em.x * OUT_DIM + q * 20];
    float4 v0 = vp[0];                                  // 5 independent gathers
    float4 v1 = vp[1];
    float4 v2 = vp[2];
    float4 v3 = vp[3];
    float4 v4 = vp[4];
    float* p = &out[(size_t)em.y * OUT_DIM + q * 20];
    redg_v4(p +  0, v0.x * nrm, v0.y * nrm, v0.z * nrm, v0.w * nrm);
    redg_v4(p +  4, v1.x * nrm, v1.y * nrm, v1.z * nrm, v1.w * nrm);
    redg_v4(p +  8, v2.x * nrm, v2.y * nrm, v2.z * nrm, v2.w * nrm);
    redg_v4(p + 12, v3.x * nrm, v3.y * nrm, v3.z * nrm, v3.w * nrm);
    redg_v4(p + 16, v4.x * nrm, v4.y * nrm, v4.z * nrm, v4.w * nrm);
}

// ---------------- launcher -------------------------------------------------
extern "C" void kernel_launch(void* const* d_in, const int* in_sizes, int n_in,
                              void* d_out, int out_size) {
    const float*    x  = (const float*)d_in[0];
    const unsigned* ei = (const unsigned*)d_in[1];   // int32 OR int64 words
    const float*    W1 = (const float*)d_in[2];
    const float*    b1 = (const float*)d_in[3];
    const float*    W2 = (const float*)d_in[4];
    const float*    b2 = (const float*)d_in[5];
    float* out = (float*)d_out;

    const int T = 256;
    k_detect  <<<1, 32>>>(ei);
    k_init_deg<<<(N_NODES + T - 1) / T, T>>>();
    k_extract <<<(N_EDGES + T - 1) / T, T>>>(ei);
    k_rsqrt   <<<(N_NODES + T - 1) / T, T>>>();
    k_em      <<<(N_EDGES + T - 1) / T, T>>>();
    k_gemm1   <<<(N_NODES + T - 1) / T, T>>>(x, W1);
    k_agg1    <<<(N_EDGES * 4 + T - 1) / T, T>>>();
    k_gemm2   <<<(N_NODES + T - 1) / T, T>>>(W2, b1, b2, out);
    k_agg2    <<<(N_EDGES * 2 + T - 1) / T, T>>>(out);
}